// round 7
// baseline (speedup 1.0000x reference)
#include <cuda_runtime.h>
#include <cuda_bf16.h>
#include <cstdint>

#define NUM_CLASSES 1000
#define FEAT_DIM    512
#define F4_PER_ROW  (FEAT_DIM / 4)     // 128
#define BATCH       32768
#define TILE        512
// ALPHA = 0.5

// Scratch (device globals, allocation-free). Zero at module load; restored to
// zero by the kernels themselves each call => deterministic across replays.
__device__ int   g_hist[NUM_CLASSES];
__device__ int   g_offsets[NUM_CLASSES];
__device__ int   g_cursor[NUM_CLASSES];
__device__ int   g_rowidx[BATCH];
__device__ float g_loss;

// ---------------------------------------------------------------------------
// 1) Histogram of labels (smem-aggregated, merged to global).
// ---------------------------------------------------------------------------
__global__ void __launch_bounds__(1024) hist_kernel(const int* __restrict__ labels)
{
    __shared__ int sh[NUM_CLASSES];
    for (int i = threadIdx.x; i < NUM_CLASSES; i += 1024) sh[i] = 0;
    __syncthreads();

    const int stride = gridDim.x * 1024;
    for (int r = blockIdx.x * 1024 + threadIdx.x; r < BATCH; r += stride)
        atomicAdd(&sh[labels[r]], 1);
    __syncthreads();

    for (int i = threadIdx.x; i < NUM_CLASSES; i += 1024) {
        int v = sh[i];
        if (v) atomicAdd(&g_hist[i], v);
    }
}

// ---------------------------------------------------------------------------
// 2) Exclusive prefix sum over 1000 counts (single block, Hillis-Steele).
// ---------------------------------------------------------------------------
__global__ void __launch_bounds__(1024) scan_kernel()
{
    __shared__ int sh[1024];
    const int t = threadIdx.x;
    sh[t] = (t < NUM_CLASSES) ? g_hist[t] : 0;
    __syncthreads();

    #pragma unroll
    for (int off = 1; off < 1024; off <<= 1) {
        int v = (t >= off) ? sh[t - off] : 0;
        __syncthreads();
        sh[t] += v;
        __syncthreads();
    }
    if (t < NUM_CLASSES) {
        int excl = sh[t] - g_hist[t];
        g_offsets[t] = excl;
        g_cursor[t]  = excl;
    }
}

// ---------------------------------------------------------------------------
// 3) Scatter row indices into class-grouped order.
// ---------------------------------------------------------------------------
__global__ void __launch_bounds__(1024) scatter_kernel(const int* __restrict__ labels)
{
    const int stride = gridDim.x * 1024;
    for (int r = blockIdx.x * 1024 + threadIdx.x; r < BATCH; r += stride) {
        int pos = atomicAdd(&g_cursor[labels[r]], 1);
        g_rowidx[pos] = r;
    }
}

// ---------------------------------------------------------------------------
// 4) Main: one 512-thread block per class, 4 row-groups of 128 threads.
//    group g = t>>7 accumulates rows j = g, g+4, ... in registers; partials
//    combined via smem. No fp atomics on the sum path. Computes the class's
//    loss term  sum||f||^2 - 2<c,s> + cnt*||c||^2  and the updated center,
//    written directly to out. Zeroes its own g_hist[c] for the next call.
// ---------------------------------------------------------------------------
__global__ void __launch_bounds__(512) class_main_kernel(
    const float* __restrict__ features,
    const float* __restrict__ centers,
    float* __restrict__ out)
{
    const int c    = blockIdx.x;
    const int t    = threadIdx.x;        // 0..511
    const int g    = t >> 7;             // row-group 0..3
    const int tc   = t & 127;            // float4 column 0..127
    const int lane = t & 31;
    const int wid  = t >> 5;             // warp 0..15

    const int cnt = g_hist[c];
    const int off = g_offsets[c];

    const float4* __restrict__ F = reinterpret_cast<const float4*>(features);

    float4 acc = make_float4(0.f, 0.f, 0.f, 0.f);
    float  sumsq = 0.f;

    __shared__ int s_idx[TILE];

    for (int base = 0; base < cnt; base += TILE) {
        const int m = min(TILE, cnt - base);
        if (t < m) s_idx[t] = g_rowidx[off + base + t];
        __syncthreads();

        int j = g;
        // unrolled x2 over this group's rows (stride 4) for MLP
        for (; j + 4 < m; j += 8) {
            const float4 v0 = F[(size_t)s_idx[j]     * F4_PER_ROW + tc];
            const float4 v1 = F[(size_t)s_idx[j + 4] * F4_PER_ROW + tc];
            acc.x += v0.x + v1.x;
            acc.y += v0.y + v1.y;
            acc.z += v0.z + v1.z;
            acc.w += v0.w + v1.w;
            sumsq += v0.x*v0.x + v0.y*v0.y + v0.z*v0.z + v0.w*v0.w;
            sumsq += v1.x*v1.x + v1.y*v1.y + v1.z*v1.z + v1.w*v1.w;
        }
        for (; j < m; j += 4) {
            const float4 v = F[(size_t)s_idx[j] * F4_PER_ROW + tc];
            acc.x += v.x; acc.y += v.y; acc.z += v.z; acc.w += v.w;
            sumsq += v.x*v.x + v.y*v.y + v.z*v.z + v.w*v.w;
        }
        __syncthreads();
    }

    // ---- combine the 4 group partials through smem ----
    __shared__ float4 s_acc[4][F4_PER_ROW];        // 8 KB
    s_acc[g][tc] = acc;

    // ---- sumsq: warp-reduce all 16 warps ----
    #pragma unroll
    for (int s = 16; s > 0; s >>= 1)
        sumsq += __shfl_xor_sync(0xffffffffu, sumsq, s);

    __shared__ float s_ws[16];
    if (lane == 0) s_ws[wid] = sumsq;
    __syncthreads();

    float lp = 0.0f;
    if (t < F4_PER_ROW) {
        float4 a0 = s_acc[0][t];
        float4 a1 = s_acc[1][t];
        float4 a2 = s_acc[2][t];
        float4 a3 = s_acc[3][t];
        float sx = a0.x + a1.x + a2.x + a3.x;
        float sy = a0.y + a1.y + a2.y + a3.y;
        float sz = a0.z + a1.z + a2.z + a3.z;
        float sw = a0.w + a1.w + a2.w + a3.w;

        const float4 cv = reinterpret_cast<const float4*>(centers)[c * F4_PER_ROW + t];
        const float fcnt = (float)cnt;

        // cross + quadratic loss terms (sumsq added by thread 0 below)
        lp = fcnt * (cv.x*cv.x + cv.y*cv.y + cv.z*cv.z + cv.w*cv.w)
           - 2.0f * (cv.x*sx + cv.y*sy + cv.z*sz + cv.w*sw);

        float ox, oy, oz, ow;
        if (cnt > 0) {
            const float inv = 0.5f / fcnt;       // ALPHA = 0.5
            ox = 0.5f * cv.x + sx * inv;
            oy = 0.5f * cv.y + sy * inv;
            oz = 0.5f * cv.z + sz * inv;
            ow = 0.5f * cv.w + sw * inv;
        } else {
            ox = cv.x; oy = cv.y; oz = cv.z; ow = cv.w;
        }
        float* o = out + 1 + (size_t)(c * F4_PER_ROW + t) * 4;
        o[0] = ox; o[1] = oy; o[2] = oz; o[3] = ow;
    }

    // ---- reduce lp over the 4 low warps ----
    #pragma unroll
    for (int s = 16; s > 0; s >>= 1)
        lp += __shfl_xor_sync(0xffffffffu, lp, s);

    __shared__ float s_lp[4];
    if (t < F4_PER_ROW && lane == 0) s_lp[wid] = lp;
    __syncthreads();

    if (t == 0) {
        float total = s_lp[0] + s_lp[1] + s_lp[2] + s_lp[3];
        #pragma unroll
        for (int w = 0; w < 16; w++) total += s_ws[w];
        atomicAdd(&g_loss, total);
        g_hist[c] = 0;                   // self-reset for next call
    }
}

// ---------------------------------------------------------------------------
// 5) Tail: loss scalar; reset g_loss.
// ---------------------------------------------------------------------------
__global__ void __launch_bounds__(32) tail_kernel(float* __restrict__ out)
{
    if (threadIdx.x == 0) {
        out[0] = 0.5f * g_loss / (float)BATCH;
        g_loss = 0.0f;
    }
}

extern "C" void kernel_launch(void* const* d_in, const int* in_sizes, int n_in,
                              void* d_out, int out_size)
{
    const float* features = (const float*)d_in[0];
    const int*   labels   = (const int*)d_in[1];
    const float* centers  = (const float*)d_in[2];
    float*       out      = (float*)d_out;

    (void)in_sizes; (void)n_in; (void)out_size;

    hist_kernel<<<16, 1024>>>(labels);
    scan_kernel<<<1, 1024>>>();
    scatter_kernel<<<32, 1024>>>(labels);
    class_main_kernel<<<NUM_CLASSES, 512>>>(features, centers, out);
    tail_kernel<<<1, 32>>>(out);
}